// round 16
// baseline (speedup 1.0000x reference)
#include <cuda_runtime.h>
#include <cuda_fp16.h>
#include <mma.h>
#include <math.h>
#include <cstdint>

using namespace nvcuda;

#define NN   100000
#define EE   3200000
#define H    64
#define DIN  15
#define DOUT 12
#define NT   5
#define GG   256
#define STEPS 6

#define RT    32                  // dst nodes per CTA
#define NCTA  (NN / RT)           // 3125
#define K2    80                  // augmented K for stage 2 (64 + bias col + pad)
#define SLD2  336                 // halves per row, staged S tile
#define WLD   72                  // smem weight row stride (halves)

#define KEYN   500000             // dst*5+type keys
#define KEYPAD 500224             // 1954 * 256
#define NB1    1954
#define NB2    8

// ---------------- scratch (device globals; no allocation) ----------------
__device__ float  g_out0[NN * H];
__device__ float  g_h[NN * H];                 // buffer A
__device__ float  g_h2[NN * H];                // buffer B
__device__ __half g_Bh[6 * K2 * H];            // aug GRU panels fp16
__device__ __half g_eembh[NT * H * H];         // Wstack [320][64] fp16
__device__ int    g_cnt5[KEYPAD];
__device__ int    g_off5[KEYN + 1];
__device__ int    g_cur5[KEYN];
__device__ int    g_packed[EE];                // src only (sorted by dst*5+type)
__device__ int    g_psum1[NB1 + 64];
__device__ int    g_pref1[NB1 + 64];
__device__ int    g_psum2[NB2];
__device__ int    g_pref2[NB2];

__device__ __forceinline__ float sigmoidf_(float v) { return 1.0f / (1.0f + expf(-v)); }

typedef wmma::fragment<wmma::matrix_a, 16, 16, 16, __half, wmma::row_major> A16;
typedef wmma::fragment<wmma::matrix_b, 16, 16, 16, __half, wmma::row_major> B16;
typedef wmma::fragment<wmma::accumulator, 16, 16, 16, float> C16;

// ---------------- misc ----------------
__global__ void zeroi_kernel(int* __restrict__ p, int n) {
    int i = blockIdx.x * blockDim.x + threadIdx.x;
    if (i < n) p[i] = 0;
}
__global__ void zerof_kernel(float* __restrict__ p, int n) {
    int i = blockIdx.x * blockDim.x + threadIdx.x;
    if (i < n) p[i] = 0.0f;
}

// ---------------- counting sort by key = dst*5 + type ----------------
__global__ void hist5_kernel(const int* __restrict__ dst, const int* __restrict__ et,
                             int* __restrict__ cnt) {
    int e = blockIdx.x * blockDim.x + threadIdx.x;
    if (e < EE) atomicAdd(&cnt[dst[e] * 5 + et[e]], 1);
}
__global__ void cs1_kernel(const int* __restrict__ cnt, int* __restrict__ psum1) {
    __shared__ int s[256];
    int t = threadIdx.x;
    s[t] = cnt[blockIdx.x * 256 + t];
    __syncthreads();
#pragma unroll
    for (int d = 128; d > 0; d >>= 1) {
        if (t < d) s[t] += s[t + d];
        __syncthreads();
    }
    if (t == 0) psum1[blockIdx.x] = s[0];
}
__global__ void cs2_kernel(const int* __restrict__ psum1, int* __restrict__ psum2) {
    __shared__ int s[256];
    int t = threadIdx.x;
    int gid = blockIdx.x * 256 + t;
    s[t] = (gid < NB1) ? psum1[gid] : 0;
    __syncthreads();
#pragma unroll
    for (int d = 128; d > 0; d >>= 1) {
        if (t < d) s[t] += s[t + d];
        __syncthreads();
    }
    if (t == 0) psum2[blockIdx.x] = s[0];
}
__global__ void scan2_kernel(const int* __restrict__ psum2, int* __restrict__ pref2) {
    if (threadIdx.x == 0) {
        int s = 0;
        for (int g = 0; g < NB2; g++) { pref2[g] = s; s += psum2[g]; }
    }
}
__global__ void scanB_kernel(const int* __restrict__ psum1, const int* __restrict__ pref2,
                             int* __restrict__ pref1) {
    __shared__ int s[256];
    int t = threadIdx.x;
    int gid = blockIdx.x * 256 + t;
    int v = (gid < NB1) ? psum1[gid] : 0;
    s[t] = v;
    __syncthreads();
#pragma unroll
    for (int d = 1; d < 256; d <<= 1) {
        int x = (t >= d) ? s[t - d] : 0;
        __syncthreads();
        s[t] += x;
        __syncthreads();
    }
    if (gid < NB1) pref1[gid] = s[t] - v + pref2[blockIdx.x];
}
__global__ void offs5_kernel(const int* __restrict__ cnt, const int* __restrict__ pref1,
                             int* __restrict__ off, int* __restrict__ cursor) {
    __shared__ int s[256];
    int t = threadIdx.x;
    int gid = blockIdx.x * 256 + t;
    int v = cnt[gid];
    s[t] = v;
    __syncthreads();
#pragma unroll
    for (int d = 1; d < 256; d <<= 1) {
        int x = (t >= d) ? s[t - d] : 0;
        __syncthreads();
        s[t] += x;
        __syncthreads();
    }
    int excl = s[t] - v + pref1[blockIdx.x];
    if (gid <= KEYN) {
        off[gid] = excl;
        if (gid < KEYN) cursor[gid] = excl;
    }
}
__global__ void place5_kernel(const int* __restrict__ src, const int* __restrict__ dst,
                              const int* __restrict__ et, int* __restrict__ cursor,
                              int* __restrict__ packed) {
    int e = blockIdx.x * blockDim.x + threadIdx.x;
    if (e < EE) {
        int pos = atomicAdd(&cursor[dst[e] * 5 + et[e]], 1);
        packed[pos] = src[e];
    }
}

// ---------------- fp16 panel prep ----------------
__global__ void bprep_kernel(const float* __restrict__ eemb,
                             const float* __restrict__ w_ih,
                             const float* __restrict__ w_hh,
                             const float* __restrict__ b_ih,
                             const float* __restrict__ b_hh,
                             __half* __restrict__ Bh,
                             __half* __restrict__ eembh) {
    int p = blockIdx.x;
    if (p < 6) {
        const float* W = (p < 3) ? w_ih : w_hh;
        const float* B = (p < 3) ? b_ih : b_hh;
        int c0 = (p % 3) * 64;
        __half* out = Bh + p * (K2 * H);
        for (int i = threadIdx.x; i < K2 * H; i += 256) {
            int k = i >> 6, n = i & 63;
            float v = 0.0f;
            if (k < 64) v = W[k * 192 + c0 + n];
            else if (k == 64) v = B[c0 + n];
            out[i] = __float2half(v);
        }
    } else {
        for (int i = threadIdx.x; i < NT * H * H; i += 256)
            eembh[i] = __float2half(eemb[i]);
    }
}

// ---------------- lin0: 16 nodes per block ----------------
__global__ __launch_bounds__(256) void lin0_kernel(const float* __restrict__ x,
                                                   const float* __restrict__ w,
                                                   const float* __restrict__ b,
                                                   float* __restrict__ out0,
                                                   float* __restrict__ h) {
    __shared__ float sw[DIN * H];
    __shared__ float sb[H];
    __shared__ float sx[16][16];
    int tid = threadIdx.x;
    for (int i = tid; i < DIN * H; i += 256) sw[i] = w[i];
    if (tid < H) sb[tid] = b[tid];
    int n0 = blockIdx.x * 16;
    if (tid < 16 * DIN) {
        int ln = tid / DIN, k = tid % DIN;
        sx[ln][k] = x[(n0 + ln) * DIN + k];
    }
    __syncthreads();
#pragma unroll
    for (int rep = 0; rep < 4; rep++) {
        int idx = tid + rep * 256;
        int ln = idx >> 6, o = idx & 63;
        int n = n0 + ln;
        float acc = sb[o];
#pragma unroll
        for (int k = 0; k < DIN; k++) acc += sx[ln][k] * sw[k * H + o];
        acc = fmaxf(acc, 0.0f);
        out0[(size_t)n * H + o] = acc;
        h[(size_t)n * H + o] = acc;
    }
}

// ======== fused step: gather + conv GEMM + GRU GEMM + gates (weights in smem) ========
// smem (bytes):
//   sS    @0       32*336*2 = 21504
//   sW    @21504   480*72*2 = 69120
//   sMf   @90624   32*80*4  = 10240
//   sAm   @100864  32*88*2  = 5632
//   sH    @106496  32*88*2  = 5632
//   sInvd @112128  32*4     = 128
#define GSMEM 112256
__global__ __launch_bounds__(256) void step_kernel(const float* __restrict__ hcur,
                                                   float* __restrict__ hnxt,
                                                   const int* __restrict__ packed,
                                                   const int* __restrict__ off5,
                                                   const float* __restrict__ cbias,
                                                   const __half* __restrict__ eembh,
                                                   const __half* __restrict__ Bh) {
    extern __shared__ char smraw[];
    __half* sS   = (__half*)smraw;
    __half* sW   = (__half*)(smraw + 21504);
    float*  sMf  = (float*)(smraw + 90624);
    __half* sAm  = (__half*)(smraw + 100864);
    __half* sH   = (__half*)(smraw + 106496);
    float*  sInvd = (float*)(smraw + 112128);

    int tid = threadIdx.x;
    int r0g = blockIdx.x * RT;
    int w = tid >> 5;
    int lid = tid & 31;

    // ---- stage h tile into fp16 K-augmented sH; invd; eembh -> sW (padded) ----
    for (int i = tid; i < RT * 80; i += 256) {
        int r = i / 80, c = i % 80;
        float v = (c < 64) ? hcur[(size_t)(r0g + r) * H + c] : ((c == 64) ? 1.0f : 0.0f);
        sH[r * 88 + c] = __float2half(v);
    }
    if (tid < RT) {
        int n5 = (r0g + tid) * 5;
        int d = off5[n5 + 5] - off5[n5];
        sInvd[tid] = 1.0f / (float)max(d, 1);
    }
    {
        const uint4* Eg = (const uint4*)eembh;
        for (int i = tid; i < 320 * 8; i += 256) {
            int r = i >> 3, q = i & 7;
            *(uint4*)(sW + r * WLD + q * 8) = Eg[i];
        }
    }

    // ---- phase 1: gather 4 nodes per warp (clean-batch fast path; MLP8; prefetch) ----
    const float2* h2 = (const float2*)hcur;
#pragma unroll
    for (int i = 0; i < 4; i++) {
        int r = w * 4 + i;
        int n5 = (r0g + r) * 5;
        int e0 = off5[n5];
        int b1 = off5[n5 + 1], b2 = off5[n5 + 2], b3 = off5[n5 + 3], b4 = off5[n5 + 4];
        int e1 = off5[n5 + 5];

        float2 acc = {0.f, 0.f};
        int nf = 0;
        int nextB = b1;
        int idx = e0;
        __half2* sp = (__half2*)(sS + r * SLD2) + lid;

        auto flush = [&]() {
            sp[nf * 32] = __float22half2_rn(acc);
            acc.x = 0.f; acc.y = 0.f;
            nf++;
            nextB = (nf == 1) ? b2 : (nf == 2) ? b3 : (nf == 3) ? b4 : 0x7FFFFFFF;
        };

        int pk = (e0 + lid < e1) ? packed[e0 + lid] : 0;
        for (int base = e0; base < e1; base += 32) {
            int nb = base + 32;
            int pk_next = (nb + lid < e1) ? packed[nb + lid] : 0;   // prefetch
            int cnt = min(32, e1 - base);
            if (nextB >= base + cnt) {
                // fast path: no type boundary inside this batch
                int j = 0;
                for (; j + 8 <= cnt; j += 8) {
                    int p0 = __shfl_sync(0xffffffffu, pk, j);
                    int p1 = __shfl_sync(0xffffffffu, pk, j + 1);
                    int p2 = __shfl_sync(0xffffffffu, pk, j + 2);
                    int p3 = __shfl_sync(0xffffffffu, pk, j + 3);
                    int p4 = __shfl_sync(0xffffffffu, pk, j + 4);
                    int p5 = __shfl_sync(0xffffffffu, pk, j + 5);
                    int p6 = __shfl_sync(0xffffffffu, pk, j + 6);
                    int p7 = __shfl_sync(0xffffffffu, pk, j + 7);
                    float2 f0 = h2[(size_t)p0 * 32 + lid];
                    float2 f1 = h2[(size_t)p1 * 32 + lid];
                    float2 f2 = h2[(size_t)p2 * 32 + lid];
                    float2 f3 = h2[(size_t)p3 * 32 + lid];
                    float2 f4 = h2[(size_t)p4 * 32 + lid];
                    float2 f5 = h2[(size_t)p5 * 32 + lid];
                    float2 f6 = h2[(size_t)p6 * 32 + lid];
                    float2 f7 = h2[(size_t)p7 * 32 + lid];
                    acc.x += f0.x + f1.x + f2.x + f3.x + f4.x + f5.x + f6.x + f7.x;
                    acc.y += f0.y + f1.y + f2.y + f3.y + f4.y + f5.y + f6.y + f7.y;
                }
                for (; j + 4 <= cnt; j += 4) {
                    int p0 = __shfl_sync(0xffffffffu, pk, j);
                    int p1 = __shfl_sync(0xffffffffu, pk, j + 1);
                    int p2 = __shfl_sync(0xffffffffu, pk, j + 2);
                    int p3 = __shfl_sync(0xffffffffu, pk, j + 3);
                    float2 f0 = h2[(size_t)p0 * 32 + lid];
                    float2 f1 = h2[(size_t)p1 * 32 + lid];
                    float2 f2 = h2[(size_t)p2 * 32 + lid];
                    float2 f3 = h2[(size_t)p3 * 32 + lid];
                    acc.x += f0.x + f1.x + f2.x + f3.x;
                    acc.y += f0.y + f1.y + f2.y + f3.y;
                }
                for (; j < cnt; j++) {
                    int p = __shfl_sync(0xffffffffu, pk, j);
                    float2 f = h2[(size_t)p * 32 + lid];
                    acc.x += f.x; acc.y += f.y;
                }
                idx += cnt;
            } else {
                // slow path: boundary(-ies) inside this batch
                int j = 0;
                for (; j + 4 <= cnt; j += 4) {
                    int p0 = __shfl_sync(0xffffffffu, pk, j);
                    int p1 = __shfl_sync(0xffffffffu, pk, j + 1);
                    int p2 = __shfl_sync(0xffffffffu, pk, j + 2);
                    int p3 = __shfl_sync(0xffffffffu, pk, j + 3);
                    float2 f0 = h2[(size_t)p0 * 32 + lid];
                    float2 f1 = h2[(size_t)p1 * 32 + lid];
                    float2 f2 = h2[(size_t)p2 * 32 + lid];
                    float2 f3 = h2[(size_t)p3 * 32 + lid];
                    while (idx == nextB) flush();
                    acc.x += f0.x; acc.y += f0.y; idx++;
                    while (idx == nextB) flush();
                    acc.x += f1.x; acc.y += f1.y; idx++;
                    while (idx == nextB) flush();
                    acc.x += f2.x; acc.y += f2.y; idx++;
                    while (idx == nextB) flush();
                    acc.x += f3.x; acc.y += f3.y; idx++;
                }
                for (; j < cnt; j++) {
                    int p = __shfl_sync(0xffffffffu, pk, j);
                    float2 f = h2[(size_t)p * 32 + lid];
                    while (idx == nextB) flush();
                    acc.x += f.x; acc.y += f.y; idx++;
                }
            }
            pk = pk_next;
        }
        while (nf < 5) flush();
    }
    __syncthreads();

    int rg = w >> 2, cg = w & 3;
    int r0 = rg * 16;
    int gr0 = r0g + r0;
    int j0 = cg * 16;

    // ---- phase 2: conv GEMM, K = 320, fp16 (B from smem) ----
    {
        C16 macc;
        wmma::fill_fragment(macc, 0.0f);
#pragma unroll
        for (int kk = 0; kk < 20; kk++) {
            A16 a;
            wmma::load_matrix_sync(a, sS + r0 * SLD2 + kk * 16, SLD2);
            B16 b;
            wmma::load_matrix_sync(b, sW + kk * 16 * WLD + j0, WLD);
            wmma::mma_sync(macc, a, b, macc);
        }
        wmma::store_matrix_sync(sMf + r0 * 80 + j0, macc, 80, wmma::mem_row_major);
    }
    __syncthreads();

    // m = relu(macc * invdeg + cbias) -> sAm fp16 (+aug cols); stage Bh -> sW
    for (int i = tid; i < RT * 80; i += 256) {
        int r = i / 80, c = i % 80;
        float v;
        if (c < 64) v = fmaxf(fmaf(sMf[r * 80 + c], sInvd[r], cbias[c]), 0.0f);
        else v = (c == 64) ? 1.0f : 0.0f;
        sAm[r * 88 + c] = __float2half(v);
    }
    {
        const uint4* Bg = (const uint4*)Bh;
        for (int i = tid; i < 480 * 8; i += 256) {
            int r = i >> 3, q = i & 7;
            *(uint4*)(sW + r * WLD + q * 8) = Bg[i];
        }
    }
    __syncthreads();

    // ---- phase 3: GRU GEMMs, K = 80, fp16 (B from smem) ----
    C16 xr, xz, xn, fr, fz, fn;
    wmma::fill_fragment(xr, 0.0f); wmma::fill_fragment(xz, 0.0f);
    wmma::fill_fragment(xn, 0.0f); wmma::fill_fragment(fr, 0.0f);
    wmma::fill_fragment(fz, 0.0f); wmma::fill_fragment(fn, 0.0f);

#pragma unroll
    for (int kk = 0; kk < 5; kk++) {
        A16 am, ah;
        wmma::load_matrix_sync(am, sAm + r0 * 88 + kk * 16, 88);
        wmma::load_matrix_sync(ah, sH + r0 * 88 + kk * 16, 88);
        const __half* bp = sW + kk * 16 * WLD + j0;
        B16 b;
        wmma::load_matrix_sync(b, bp, WLD);                    wmma::mma_sync(xr, am, b, xr);
        wmma::load_matrix_sync(b, bp + 1 * K2 * WLD, WLD);     wmma::mma_sync(xz, am, b, xz);
        wmma::load_matrix_sync(b, bp + 2 * K2 * WLD, WLD);     wmma::mma_sync(xn, am, b, xn);
        wmma::load_matrix_sync(b, bp + 3 * K2 * WLD, WLD);     wmma::mma_sync(fr, ah, b, fr);
        wmma::load_matrix_sync(b, bp + 4 * K2 * WLD, WLD);     wmma::mma_sync(fz, ah, b, fz);
        wmma::load_matrix_sync(b, bp + 5 * K2 * WLD, WLD);     wmma::mma_sync(fn, ah, b, fn);
    }

    C16 hold;
    wmma::load_matrix_sync(hold, hcur + (size_t)gr0 * H + j0, H, wmma::mem_row_major);
#pragma unroll
    for (int t = 0; t < hold.num_elements; t++) {
        float r = sigmoidf_(xr.x[t] + fr.x[t]);
        float z = sigmoidf_(xz.x[t] + fz.x[t]);
        float nv = tanhf(xn.x[t] + r * fn.x[t]);
        hold.x[t] = (1.0f - z) * nv + z * hold.x[t];
    }
    wmma::store_matrix_sync(hnxt + (size_t)gr0 * H + j0, hold, H, wmma::mem_row_major);
}

// ======== fused readout: t1/t2 GEMMs + DOUT projection + segment-sum ========
// smem (bytes): sA@0 33280 (128*65f) | sB@33280 32768 (128*64f) |
//               st1@66048 17408 (64*68f) | st2@83456 17408 | total 100864
#define RSMEM 100864
__global__ __launch_bounds__(256) void fused_readout_kernel(
    const float* __restrict__ hmat, const float* __restrict__ out0,
    const int* __restrict__ batch,
    const float* __restrict__ i_w1, const float* __restrict__ i_b1,
    const float* __restrict__ i_w2, const float* __restrict__ i_b2,
    const float* __restrict__ j_w1, const float* __restrict__ j_b1,
    const float* __restrict__ j_w2, const float* __restrict__ j_b2,
    float* __restrict__ out) {
    extern __shared__ char smraw[];
    float* sA  = (float*)smraw;
    float* sB  = (float*)(smraw + 33280);
    float* st1 = (float*)(smraw + 66048);
    float* st2 = (float*)(smraw + 83456);

    const int tid = threadIdx.x;
    const int m0 = blockIdx.x * 64;
    const int tx = tid % 16, ty = tid / 16;

    // ===== pass A: t1 = sigmoid(concat(h, out0) @ i_w1 + i_b1), K=128 =====
    {
#pragma unroll
        for (int r = 0; r < 8; r++) {            // KQ=32, 32*64/256=8 iters
            int i = tid + 256 * r;
            int m = i / 32, kq = i % 32;
            int gm = m0 + m;
            float4 v = make_float4(0.f, 0.f, 0.f, 0.f);
            if (gm < NN) {
                if (kq < 16) v = *(const float4*)(hmat + (size_t)gm * 64 + kq * 4);
                else v = *(const float4*)(out0 + (size_t)gm * 64 + (kq - 16) * 4);
            }
            int k = kq * 4;
            sA[(k + 0) * 65 + m] = v.x; sA[(k + 1) * 65 + m] = v.y;
            sA[(k + 2) * 65 + m] = v.z; sA[(k + 3) * 65 + m] = v.w;
        }
#pragma unroll
        for (int r = 0; r < 8; r++) {            // 128 rows * 16 f4 / 256
            int i = tid + 256 * r;
            int k = i / 16, n4 = i % 16;
            *(float4*)(sB + k * 64 + n4 * 4) = *(const float4*)(i_w1 + (size_t)k * 64 + n4 * 4);
        }
        __syncthreads();
        float acc[4][4];
#pragma unroll
        for (int a = 0; a < 4; a++)
#pragma unroll
            for (int b = 0; b < 4; b++) acc[a][b] = 0.0f;
#pragma unroll 8
        for (int k = 0; k < 128; k++) {
            float a0 = sA[k * 65 + ty * 4 + 0];
            float a1 = sA[k * 65 + ty * 4 + 1];
            float a2 = sA[k * 65 + ty * 4 + 2];
            float a3 = sA[k * 65 + ty * 4 + 3];
            float4 bv = *(const float4*)(sB + k * 64 + tx * 4);
            acc[0][0] += a0 * bv.x; acc[0][1] += a0 * bv.y; acc[0][2] += a0 * bv.z; acc[0][3] += a0 * bv.w;
            acc[1][0] += a1 * bv.x; acc[1][1] += a1 * bv.y; acc[1][2] += a1 * bv.z; acc[1][3] += a1 * bv.w;
            acc[2][0] += a2 * bv.x; acc[2][1] += a2 * bv.y; acc[2][2] += a2 * bv.z; acc[2][3] += a2 * bv.w;
            acc[3][0] += a3 * bv.x; acc[3][1] += a3 * bv.y; acc[3][2] += a3 * bv.z; acc[3][3] += a3 * bv.w;
        }
#pragma unroll
        for (int a = 0; a < 4; a++) {
            int row = ty * 4 + a;
#pragma unroll
            for (int b = 0; b < 4; b++)
                st1[row * 68 + tx * 4 + b] = sigmoidf_(acc[a][b] + i_b1[tx * 4 + b]);
        }
    }
    __syncthreads();

    // ===== pass B: t2 = sigmoid(h @ j_w1 + j_b1), K=64 =====
    {
#pragma unroll
        for (int r = 0; r < 4; r++) {            // KQ=16, 16*64/256=4 iters
            int i = tid + 256 * r;
            int m = i / 16, kq = i % 16;
            int gm = m0 + m;
            float4 v = make_float4(0.f, 0.f, 0.f, 0.f);
            if (gm < NN) v = *(const float4*)(hmat + (size_t)gm * 64 + kq * 4);
            int k = kq * 4;
            sA[(k + 0) * 65 + m] = v.x; sA[(k + 1) * 65 + m] = v.y;
            sA[(k + 2) * 65 + m] = v.z; sA[(k + 3) * 65 + m] = v.w;
        }
#pragma unroll
        for (int r = 0; r < 4; r++) {
            int i = tid + 256 * r;
            int k = i / 16, n4 = i % 16;
            *(float4*)(sB + k * 64 + n4 * 4) = *(const float4*)(j_w1 + (size_t)k * 64 + n4 * 4);
        }
        __syncthreads();
        float acc[4][4];
#pragma unroll
        for (int a = 0; a < 4; a++)
#pragma unroll
            for (int b = 0; b < 4; b++) acc[a][b] = 0.0f;
#pragma unroll 8
        for (int k = 0; k < 64; k++) {
            float a0 = sA[k * 65 + ty * 4 + 0];
            float a1 = sA[k * 65 + ty * 4 + 1];
            float a2 = sA[k * 65 + ty * 4 + 2];
            float a3 = sA[k * 65 + ty * 4 + 3];
            float4 bv = *(const float4*)(sB + k * 64 + tx * 4);
            acc[0][0] += a0 * bv.x; acc[0][1] += a0 * bv.y; acc[0][2] += a0 * bv.z; acc[0][3] += a0 * bv.w;
            acc[1][0] += a1 * bv.x; acc[1][1] += a1 * bv.y; acc[1][2] += a1 * bv.z; acc[1][3] += a1 * bv.w;
            acc[2][0] += a2 * bv.x; acc[2][1] += a2 * bv.y; acc[2][2] += a2 * bv.z; acc[2][3] += a2 * bv.w;
            acc[3][0] += a3 * bv.x; acc[3][1] += a3 * bv.y; acc[3][2] += a3 * bv.z; acc[3][3] += a3 * bv.w;
        }
#pragma unroll
        for (int a = 0; a < 4; a++) {
            int row = ty * 4 + a;
#pragma unroll
            for (int b = 0; b < 4; b++)
                st2[row * 68 + tx * 4 + b] = sigmoidf_(acc[a][b] + j_b1[tx * 4 + b]);
        }
    }
    __syncthreads();

    // ===== pass C: per-node DOUT projection + atomic segment-sum =====
    float* wA = sA;            // 64*12
    float* wB = sA + 768;      // 64*12
    float* bA = sA + 1536;     // 12
    float* bB = sA + 1552;     // 12
    for (int i = tid; i < 768; i += 256) { wA[i] = i_w2[i]; wB[i] = j_w2[i]; }
    if (tid < DOUT) { bA[tid] = i_b2[tid]; bB[tid] = j_b2[tid]; }
    __syncthreads();

    int ln = tid >> 2, q = tid & 3;   // node-in-block, output quarter (3 outs each)
    int n = m0 + ln;
    if (n < NN) {
        int c0 = q * 3;
        float ai[3], aj[3];
#pragma unroll
        for (int c = 0; c < 3; c++) { ai[c] = bA[c0 + c]; aj[c] = bB[c0 + c]; }
        const float* r1 = st1 + ln * 68;
        const float* r2 = st2 + ln * 68;
#pragma unroll 4
        for (int k = 0; k < 64; k++) {
            float a = r1[k], b = r2[k];
#pragma unroll
            for (int c = 0; c < 3; c++) {
                ai[c] += a * wA[k * DOUT + c0 + c];
                aj[c] += b * wB[k * DOUT + c0 + c];
            }
        }
        float* ob = out + (size_t)batch[n] * DOUT + c0;
#pragma unroll
        for (int c = 0; c < 3; c++)
            atomicAdd(&ob[c], sigmoidf_(ai[c]) * aj[c]);
    }
}

// ---------------- launch ----------------
extern "C" void kernel_launch(void* const* d_in, const int* in_sizes, int n_in,
                              void* d_out, int out_size) {
    const float* x      = (const float*)d_in[0];
    const int*   ei     = (const int*)d_in[1];
    const int*   ea     = (const int*)d_in[2];
    const int*   batch  = (const int*)d_in[3];
    const float* lin0_w = (const float*)d_in[4];
    const float* lin0_b = (const float*)d_in[5];
    const float* eemb   = (const float*)d_in[6];
    const float* cbias  = (const float*)d_in[7];
    const float* w_ih   = (const float*)d_in[8];
    const float* w_hh   = (const float*)d_in[9];
    const float* b_ih   = (const float*)d_in[10];
    const float* b_hh   = (const float*)d_in[11];
    const float* i_w1   = (const float*)d_in[12];
    const float* i_b1   = (const float*)d_in[13];
    const float* i_w2   = (const float*)d_in[14];
    const float* i_b2   = (const float*)d_in[15];
    const float* j_w1   = (const float*)d_in[16];
    const float* j_b1   = (const float*)d_in[17];
    const float* j_w2   = (const float*)d_in[18];
    const float* j_b2   = (const float*)d_in[19];
    const int* src = ei;
    const int* dst = ei + EE;
    float* out = (float*)d_out;

    float *ph, *ph2, *pout0;
    __half *pBh, *peembh;
    int *pcnt5, *poff5, *pcur5, *ppk, *ppsum1, *ppref1, *ppsum2, *ppref2;
    cudaGetSymbolAddress((void**)&ph,     g_h);
    cudaGetSymbolAddress((void**)&ph2,    g_h2);
    cudaGetSymbolAddress((void**)&pout0,  g_out0);
    cudaGetSymbolAddress((void**)&pBh,    g_Bh);
    cudaGetSymbolAddress((void**)&peembh, g_eembh);
    cudaGetSymbolAddress((void**)&pcnt5,  g_cnt5);
    cudaGetSymbolAddress((void**)&poff5,  g_off5);
    cudaGetSymbolAddress((void**)&pcur5,  g_cur5);
    cudaGetSymbolAddress((void**)&ppk,    g_packed);
    cudaGetSymbolAddress((void**)&ppsum1, g_psum1);
    cudaGetSymbolAddress((void**)&ppref1, g_pref1);
    cudaGetSymbolAddress((void**)&ppsum2, g_psum2);
    cudaGetSymbolAddress((void**)&ppref2, g_pref2);

    cudaFuncSetAttribute(step_kernel,
                         cudaFuncAttributeMaxDynamicSharedMemorySize, GSMEM);
    cudaFuncSetAttribute(fused_readout_kernel,
                         cudaFuncAttributeMaxDynamicSharedMemorySize, RSMEM);

    // ---- once-per-call preprocessing ----
    bprep_kernel<<<7, 256>>>(eemb, w_ih, w_hh, b_ih, b_hh, pBh, peembh);
    zeroi_kernel<<<(KEYPAD + 255) / 256, 256>>>(pcnt5, KEYPAD);
    zerof_kernel<<<(GG * DOUT + 255) / 256, 256>>>(out, GG * DOUT);
    lin0_kernel<<<NN / 16, 256>>>(x, lin0_w, lin0_b, pout0, ph);
    hist5_kernel<<<(EE + 255) / 256, 256>>>(dst, ea, pcnt5);
    cs1_kernel<<<NB1, 256>>>(pcnt5, ppsum1);
    cs2_kernel<<<NB2, 256>>>(ppsum1, ppsum2);
    scan2_kernel<<<1, 32>>>(ppsum2, ppref2);
    scanB_kernel<<<NB2, 256>>>(ppsum1, ppref2, ppref1);
    offs5_kernel<<<NB1, 256>>>(pcnt5, ppref1, poff5, pcur5);
    place5_kernel<<<(EE + 255) / 256, 256>>>(src, dst, ea, pcur5, ppk);

    // ---- propagation steps (double-buffered h; 6 steps end back in g_h) ----
    float* cur = ph;
    float* nxt = ph2;
    for (int s = 0; s < STEPS; s++) {
        step_kernel<<<NCTA, 256, GSMEM>>>(cur, nxt, ppk, poff5, cbias, peembh, pBh);
        float* tmp = cur; cur = nxt; nxt = tmp;
    }

    // ---- fused readout ----
    const int MB = (NN + 63) / 64;
    fused_readout_kernel<<<MB, 256, RSMEM>>>(
        cur, pout0, batch, i_w1, i_b1, i_w2, i_b2, j_w1, j_b1, j_w2, j_b2, out);
}

// round 17
// speedup vs baseline: 1.0687x; 1.0687x over previous
#include <cuda_runtime.h>
#include <cuda_fp16.h>
#include <mma.h>
#include <math.h>
#include <cstdint>

using namespace nvcuda;

#define NN   100000
#define EE   3200000
#define H    64
#define DIN  15
#define DOUT 12
#define NT   5
#define GG   256
#define STEPS 6

#define RT    32                  // dst nodes per CTA
#define NCTA  (NN / RT)           // 3125
#define K2    80                  // augmented K for stage 2 (64 + bias col + pad)
#define SLD2  336                 // halves per row, staged S tile
#define WLD   72                  // smem weight row stride (halves)

#define KEYN   500000             // dst*5+type keys
#define KEYPAD 500224             // 1954 * 256
#define NB1    1954
#define NB2    8

// ---------------- scratch (device globals; no allocation) ----------------
__device__ float  g_out0[NN * H];
__device__ float  g_h[NN * H];                 // buffer A
__device__ float  g_h2[NN * H];                // buffer B
__device__ __half g_Bh[6 * K2 * H];            // aug GRU panels fp16
__device__ __half g_eembh[NT * H * H];         // Wstack [320][64] fp16
__device__ int    g_cnt5[KEYPAD];
__device__ int    g_off5[KEYN + 1];
__device__ int    g_cur5[KEYN];
__device__ int    g_packed[EE];                // src only (sorted by dst*5+type)
__device__ int    g_psum1[NB1 + 64];
__device__ int    g_pref1[NB1 + 64];
__device__ int    g_psum2[NB2];
__device__ int    g_pref2[NB2];

__device__ __forceinline__ float sigmoidf_(float v) { return 1.0f / (1.0f + expf(-v)); }

typedef wmma::fragment<wmma::matrix_a, 16, 16, 16, __half, wmma::row_major> A16;
typedef wmma::fragment<wmma::matrix_b, 16, 16, 16, __half, wmma::row_major> B16;
typedef wmma::fragment<wmma::accumulator, 16, 16, 16, float> C16;

// ---------------- misc ----------------
__global__ void zeroi_kernel(int* __restrict__ p, int n) {
    int i = blockIdx.x * blockDim.x + threadIdx.x;
    if (i < n) p[i] = 0;
}
__global__ void zerof_kernel(float* __restrict__ p, int n) {
    int i = blockIdx.x * blockDim.x + threadIdx.x;
    if (i < n) p[i] = 0.0f;
}

// ---------------- counting sort by key = dst*5 + type ----------------
__global__ void hist5_kernel(const int* __restrict__ dst, const int* __restrict__ et,
                             int* __restrict__ cnt) {
    int e = blockIdx.x * blockDim.x + threadIdx.x;
    if (e < EE) atomicAdd(&cnt[dst[e] * 5 + et[e]], 1);
}
__global__ void cs1_kernel(const int* __restrict__ cnt, int* __restrict__ psum1) {
    __shared__ int s[256];
    int t = threadIdx.x;
    s[t] = cnt[blockIdx.x * 256 + t];
    __syncthreads();
#pragma unroll
    for (int d = 128; d > 0; d >>= 1) {
        if (t < d) s[t] += s[t + d];
        __syncthreads();
    }
    if (t == 0) psum1[blockIdx.x] = s[0];
}
__global__ void cs2_kernel(const int* __restrict__ psum1, int* __restrict__ psum2) {
    __shared__ int s[256];
    int t = threadIdx.x;
    int gid = blockIdx.x * 256 + t;
    s[t] = (gid < NB1) ? psum1[gid] : 0;
    __syncthreads();
#pragma unroll
    for (int d = 128; d > 0; d >>= 1) {
        if (t < d) s[t] += s[t + d];
        __syncthreads();
    }
    if (t == 0) psum2[blockIdx.x] = s[0];
}
__global__ void scan2_kernel(const int* __restrict__ psum2, int* __restrict__ pref2) {
    if (threadIdx.x == 0) {
        int s = 0;
        for (int g = 0; g < NB2; g++) { pref2[g] = s; s += psum2[g]; }
    }
}
__global__ void scanB_kernel(const int* __restrict__ psum1, const int* __restrict__ pref2,
                             int* __restrict__ pref1) {
    __shared__ int s[256];
    int t = threadIdx.x;
    int gid = blockIdx.x * 256 + t;
    int v = (gid < NB1) ? psum1[gid] : 0;
    s[t] = v;
    __syncthreads();
#pragma unroll
    for (int d = 1; d < 256; d <<= 1) {
        int x = (t >= d) ? s[t - d] : 0;
        __syncthreads();
        s[t] += x;
        __syncthreads();
    }
    if (gid < NB1) pref1[gid] = s[t] - v + pref2[blockIdx.x];
}
__global__ void offs5_kernel(const int* __restrict__ cnt, const int* __restrict__ pref1,
                             int* __restrict__ off, int* __restrict__ cursor) {
    __shared__ int s[256];
    int t = threadIdx.x;
    int gid = blockIdx.x * 256 + t;
    int v = cnt[gid];
    s[t] = v;
    __syncthreads();
#pragma unroll
    for (int d = 1; d < 256; d <<= 1) {
        int x = (t >= d) ? s[t - d] : 0;
        __syncthreads();
        s[t] += x;
        __syncthreads();
    }
    int excl = s[t] - v + pref1[blockIdx.x];
    if (gid <= KEYN) {
        off[gid] = excl;
        if (gid < KEYN) cursor[gid] = excl;
    }
}
__global__ void place5_kernel(const int* __restrict__ src, const int* __restrict__ dst,
                              const int* __restrict__ et, int* __restrict__ cursor,
                              int* __restrict__ packed) {
    int e = blockIdx.x * blockDim.x + threadIdx.x;
    if (e < EE) {
        int pos = atomicAdd(&cursor[dst[e] * 5 + et[e]], 1);
        packed[pos] = src[e];
    }
}

// ---------------- fp16 panel prep ----------------
__global__ void bprep_kernel(const float* __restrict__ eemb,
                             const float* __restrict__ w_ih,
                             const float* __restrict__ w_hh,
                             const float* __restrict__ b_ih,
                             const float* __restrict__ b_hh,
                             __half* __restrict__ Bh,
                             __half* __restrict__ eembh) {
    int p = blockIdx.x;
    if (p < 6) {
        const float* W = (p < 3) ? w_ih : w_hh;
        const float* B = (p < 3) ? b_ih : b_hh;
        int c0 = (p % 3) * 64;
        __half* out = Bh + p * (K2 * H);
        for (int i = threadIdx.x; i < K2 * H; i += 256) {
            int k = i >> 6, n = i & 63;
            float v = 0.0f;
            if (k < 64) v = W[k * 192 + c0 + n];
            else if (k == 64) v = B[c0 + n];
            out[i] = __float2half(v);
        }
    } else {
        for (int i = threadIdx.x; i < NT * H * H; i += 256)
            eembh[i] = __float2half(eemb[i]);
    }
}

// ---------------- lin0: 16 nodes per block ----------------
__global__ __launch_bounds__(256) void lin0_kernel(const float* __restrict__ x,
                                                   const float* __restrict__ w,
                                                   const float* __restrict__ b,
                                                   float* __restrict__ out0,
                                                   float* __restrict__ h) {
    __shared__ float sw[DIN * H];
    __shared__ float sb[H];
    __shared__ float sx[16][16];
    int tid = threadIdx.x;
    for (int i = tid; i < DIN * H; i += 256) sw[i] = w[i];
    if (tid < H) sb[tid] = b[tid];
    int n0 = blockIdx.x * 16;
    if (tid < 16 * DIN) {
        int ln = tid / DIN, k = tid % DIN;
        sx[ln][k] = x[(n0 + ln) * DIN + k];
    }
    __syncthreads();
#pragma unroll
    for (int rep = 0; rep < 4; rep++) {
        int idx = tid + rep * 256;
        int ln = idx >> 6, o = idx & 63;
        int n = n0 + ln;
        float acc = sb[o];
#pragma unroll
        for (int k = 0; k < DIN; k++) acc += sx[ln][k] * sw[k * H + o];
        acc = fmaxf(acc, 0.0f);
        out0[(size_t)n * H + o] = acc;
        h[(size_t)n * H + o] = acc;
    }
}

// ======== fused step: gather + conv GEMM + GRU GEMM + gates (weights in smem) ========
// smem (bytes):
//   sS    @0       32*336*2 = 21504
//   sW    @21504   480*72*2 = 69120
//   sMf   @90624   32*80*4  = 10240
//   sAm   @100864  32*88*2  = 5632
//   sH    @106496  32*88*2  = 5632
//   sInvd @112128  32*4     = 128
#define GSMEM 112256
__global__ __launch_bounds__(256) void step_kernel(const float* __restrict__ hcur,
                                                   float* __restrict__ hnxt,
                                                   const int* __restrict__ packed,
                                                   const int* __restrict__ off5,
                                                   const float* __restrict__ cbias,
                                                   const __half* __restrict__ eembh,
                                                   const __half* __restrict__ Bh) {
    extern __shared__ char smraw[];
    __half* sS   = (__half*)smraw;
    __half* sW   = (__half*)(smraw + 21504);
    float*  sMf  = (float*)(smraw + 90624);
    __half* sAm  = (__half*)(smraw + 100864);
    __half* sH   = (__half*)(smraw + 106496);
    float*  sInvd = (float*)(smraw + 112128);

    int tid = threadIdx.x;
    int r0g = blockIdx.x * RT;
    int w = tid >> 5;
    int lid = tid & 31;

    // ---- stage h tile into fp16 K-augmented sH; invd; eembh -> sW (padded) ----
    for (int i = tid; i < RT * 80; i += 256) {
        int r = i / 80, c = i % 80;
        float v = (c < 64) ? hcur[(size_t)(r0g + r) * H + c] : ((c == 64) ? 1.0f : 0.0f);
        sH[r * 88 + c] = __float2half(v);
    }
    if (tid < RT) {
        int n5 = (r0g + tid) * 5;
        int d = off5[n5 + 5] - off5[n5];
        sInvd[tid] = 1.0f / (float)max(d, 1);
    }
    {
        const uint4* Eg = (const uint4*)eembh;
        for (int i = tid; i < 320 * 8; i += 256) {
            int r = i >> 3, q = i & 7;
            *(uint4*)(sW + r * WLD + q * 8) = Eg[i];
        }
    }

    // ---- phase 1: gather 4 nodes per warp (type-boundary flush; MLP8; prefetch) ----
    const float2* h2 = (const float2*)hcur;
#pragma unroll
    for (int i = 0; i < 4; i++) {
        int r = w * 4 + i;
        int n5 = (r0g + r) * 5;
        int e0 = off5[n5];
        int b1 = off5[n5 + 1], b2 = off5[n5 + 2], b3 = off5[n5 + 3], b4 = off5[n5 + 4];
        int e1 = off5[n5 + 5];

        float2 acc = {0.f, 0.f};
        int nf = 0;
        int nextB = b1;
        int idx = e0;
        __half2* sp = (__half2*)(sS + r * SLD2) + lid;

        auto flush = [&]() {
            sp[nf * 32] = __float22half2_rn(acc);
            acc.x = 0.f; acc.y = 0.f;
            nf++;
            nextB = (nf == 1) ? b2 : (nf == 2) ? b3 : (nf == 3) ? b4 : 0x7FFFFFFF;
        };

        int pk = (e0 + lid < e1) ? packed[e0 + lid] : 0;
        for (int base = e0; base < e1; base += 32) {
            int nb = base + 32;
            int pk_next = (nb + lid < e1) ? packed[nb + lid] : 0;   // prefetch
            int cnt = min(32, e1 - base);
            int j = 0;
            for (; j + 8 <= cnt; j += 8) {
                int p0 = __shfl_sync(0xffffffffu, pk, j);
                int p1 = __shfl_sync(0xffffffffu, pk, j + 1);
                int p2 = __shfl_sync(0xffffffffu, pk, j + 2);
                int p3 = __shfl_sync(0xffffffffu, pk, j + 3);
                int p4 = __shfl_sync(0xffffffffu, pk, j + 4);
                int p5 = __shfl_sync(0xffffffffu, pk, j + 5);
                int p6 = __shfl_sync(0xffffffffu, pk, j + 6);
                int p7 = __shfl_sync(0xffffffffu, pk, j + 7);
                float2 f0 = h2[(size_t)p0 * 32 + lid];
                float2 f1 = h2[(size_t)p1 * 32 + lid];
                float2 f2 = h2[(size_t)p2 * 32 + lid];
                float2 f3 = h2[(size_t)p3 * 32 + lid];
                float2 f4 = h2[(size_t)p4 * 32 + lid];
                float2 f5 = h2[(size_t)p5 * 32 + lid];
                float2 f6 = h2[(size_t)p6 * 32 + lid];
                float2 f7 = h2[(size_t)p7 * 32 + lid];
                while (idx == nextB) flush();
                acc.x += f0.x; acc.y += f0.y; idx++;
                while (idx == nextB) flush();
                acc.x += f1.x; acc.y += f1.y; idx++;
                while (idx == nextB) flush();
                acc.x += f2.x; acc.y += f2.y; idx++;
                while (idx == nextB) flush();
                acc.x += f3.x; acc.y += f3.y; idx++;
                while (idx == nextB) flush();
                acc.x += f4.x; acc.y += f4.y; idx++;
                while (idx == nextB) flush();
                acc.x += f5.x; acc.y += f5.y; idx++;
                while (idx == nextB) flush();
                acc.x += f6.x; acc.y += f6.y; idx++;
                while (idx == nextB) flush();
                acc.x += f7.x; acc.y += f7.y; idx++;
            }
            for (; j + 4 <= cnt; j += 4) {
                int p0 = __shfl_sync(0xffffffffu, pk, j);
                int p1 = __shfl_sync(0xffffffffu, pk, j + 1);
                int p2 = __shfl_sync(0xffffffffu, pk, j + 2);
                int p3 = __shfl_sync(0xffffffffu, pk, j + 3);
                float2 f0 = h2[(size_t)p0 * 32 + lid];
                float2 f1 = h2[(size_t)p1 * 32 + lid];
                float2 f2 = h2[(size_t)p2 * 32 + lid];
                float2 f3 = h2[(size_t)p3 * 32 + lid];
                while (idx == nextB) flush();
                acc.x += f0.x; acc.y += f0.y; idx++;
                while (idx == nextB) flush();
                acc.x += f1.x; acc.y += f1.y; idx++;
                while (idx == nextB) flush();
                acc.x += f2.x; acc.y += f2.y; idx++;
                while (idx == nextB) flush();
                acc.x += f3.x; acc.y += f3.y; idx++;
            }
            for (; j < cnt; j++) {
                int p = __shfl_sync(0xffffffffu, pk, j);
                float2 f = h2[(size_t)p * 32 + lid];
                while (idx == nextB) flush();
                acc.x += f.x; acc.y += f.y; idx++;
            }
            pk = pk_next;
        }
        while (nf < 5) flush();
    }
    __syncthreads();

    int rg = w >> 2, cg = w & 3;
    int r0 = rg * 16;
    int gr0 = r0g + r0;
    int j0 = cg * 16;

    // ---- phase 2: conv GEMM, K = 320, fp16 (B from smem) ----
    {
        C16 macc;
        wmma::fill_fragment(macc, 0.0f);
#pragma unroll
        for (int kk = 0; kk < 20; kk++) {
            A16 a;
            wmma::load_matrix_sync(a, sS + r0 * SLD2 + kk * 16, SLD2);
            B16 b;
            wmma::load_matrix_sync(b, sW + kk * 16 * WLD + j0, WLD);
            wmma::mma_sync(macc, a, b, macc);
        }
        wmma::store_matrix_sync(sMf + r0 * 80 + j0, macc, 80, wmma::mem_row_major);
    }
    __syncthreads();

    // m = relu(macc * invdeg + cbias) -> sAm fp16 (+aug cols); stage Bh -> sW
    for (int i = tid; i < RT * 80; i += 256) {
        int r = i / 80, c = i % 80;
        float v;
        if (c < 64) v = fmaxf(fmaf(sMf[r * 80 + c], sInvd[r], cbias[c]), 0.0f);
        else v = (c == 64) ? 1.0f : 0.0f;
        sAm[r * 88 + c] = __float2half(v);
    }
    {
        const uint4* Bg = (const uint4*)Bh;
        for (int i = tid; i < 480 * 8; i += 256) {
            int r = i >> 3, q = i & 7;
            *(uint4*)(sW + r * WLD + q * 8) = Bg[i];
        }
    }
    __syncthreads();

    // ---- phase 3: GRU GEMMs, K = 80, fp16 (B from smem) ----
    C16 xr, xz, xn, fr, fz, fn;
    wmma::fill_fragment(xr, 0.0f); wmma::fill_fragment(xz, 0.0f);
    wmma::fill_fragment(xn, 0.0f); wmma::fill_fragment(fr, 0.0f);
    wmma::fill_fragment(fz, 0.0f); wmma::fill_fragment(fn, 0.0f);

#pragma unroll
    for (int kk = 0; kk < 5; kk++) {
        A16 am, ah;
        wmma::load_matrix_sync(am, sAm + r0 * 88 + kk * 16, 88);
        wmma::load_matrix_sync(ah, sH + r0 * 88 + kk * 16, 88);
        const __half* bp = sW + kk * 16 * WLD + j0;
        B16 b;
        wmma::load_matrix_sync(b, bp, WLD);                    wmma::mma_sync(xr, am, b, xr);
        wmma::load_matrix_sync(b, bp + 1 * K2 * WLD, WLD);     wmma::mma_sync(xz, am, b, xz);
        wmma::load_matrix_sync(b, bp + 2 * K2 * WLD, WLD);     wmma::mma_sync(xn, am, b, xn);
        wmma::load_matrix_sync(b, bp + 3 * K2 * WLD, WLD);     wmma::mma_sync(fr, ah, b, fr);
        wmma::load_matrix_sync(b, bp + 4 * K2 * WLD, WLD);     wmma::mma_sync(fz, ah, b, fz);
        wmma::load_matrix_sync(b, bp + 5 * K2 * WLD, WLD);     wmma::mma_sync(fn, ah, b, fn);
    }

    C16 hold;
    wmma::load_matrix_sync(hold, hcur + (size_t)gr0 * H + j0, H, wmma::mem_row_major);
#pragma unroll
    for (int t = 0; t < hold.num_elements; t++) {
        float r = sigmoidf_(xr.x[t] + fr.x[t]);
        float z = sigmoidf_(xz.x[t] + fz.x[t]);
        float nv = tanhf(xn.x[t] + r * fn.x[t]);
        hold.x[t] = (1.0f - z) * nv + z * hold.x[t];
    }
    wmma::store_matrix_sync(hnxt + (size_t)gr0 * H + j0, hold, H, wmma::mem_row_major);
}

// ======== fused readout: t1/t2 GEMMs + DOUT projection + segment-sum ========
// smem (bytes): sA@0 33280 (128*65f) | sB@33280 32768 (128*64f) |
//               st1@66048 17408 (64*68f) | st2@83456 17408 | total 100864
#define RSMEM 100864
__global__ __launch_bounds__(256) void fused_readout_kernel(
    const float* __restrict__ hmat, const float* __restrict__ out0,
    const int* __restrict__ batch,
    const float* __restrict__ i_w1, const float* __restrict__ i_b1,
    const float* __restrict__ i_w2, const float* __restrict__ i_b2,
    const float* __restrict__ j_w1, const float* __restrict__ j_b1,
    const float* __restrict__ j_w2, const float* __restrict__ j_b2,
    float* __restrict__ out) {
    extern __shared__ char smraw[];
    float* sA  = (float*)smraw;
    float* sB  = (float*)(smraw + 33280);
    float* st1 = (float*)(smraw + 66048);
    float* st2 = (float*)(smraw + 83456);

    const int tid = threadIdx.x;
    const int m0 = blockIdx.x * 64;
    const int tx = tid % 16, ty = tid / 16;

    // ===== pass A: t1 = sigmoid(concat(h, out0) @ i_w1 + i_b1), K=128 =====
    {
#pragma unroll
        for (int r = 0; r < 8; r++) {
            int i = tid + 256 * r;
            int m = i / 32, kq = i % 32;
            int gm = m0 + m;
            float4 v = make_float4(0.f, 0.f, 0.f, 0.f);
            if (gm < NN) {
                if (kq < 16) v = *(const float4*)(hmat + (size_t)gm * 64 + kq * 4);
                else v = *(const float4*)(out0 + (size_t)gm * 64 + (kq - 16) * 4);
            }
            int k = kq * 4;
            sA[(k + 0) * 65 + m] = v.x; sA[(k + 1) * 65 + m] = v.y;
            sA[(k + 2) * 65 + m] = v.z; sA[(k + 3) * 65 + m] = v.w;
        }
#pragma unroll
        for (int r = 0; r < 8; r++) {
            int i = tid + 256 * r;
            int k = i / 16, n4 = i % 16;
            *(float4*)(sB + k * 64 + n4 * 4) = *(const float4*)(i_w1 + (size_t)k * 64 + n4 * 4);
        }
        __syncthreads();
        float acc[4][4];
#pragma unroll
        for (int a = 0; a < 4; a++)
#pragma unroll
            for (int b = 0; b < 4; b++) acc[a][b] = 0.0f;
#pragma unroll 8
        for (int k = 0; k < 128; k++) {
            float a0 = sA[k * 65 + ty * 4 + 0];
            float a1 = sA[k * 65 + ty * 4 + 1];
            float a2 = sA[k * 65 + ty * 4 + 2];
            float a3 = sA[k * 65 + ty * 4 + 3];
            float4 bv = *(const float4*)(sB + k * 64 + tx * 4);
            acc[0][0] += a0 * bv.x; acc[0][1] += a0 * bv.y; acc[0][2] += a0 * bv.z; acc[0][3] += a0 * bv.w;
            acc[1][0] += a1 * bv.x; acc[1][1] += a1 * bv.y; acc[1][2] += a1 * bv.z; acc[1][3] += a1 * bv.w;
            acc[2][0] += a2 * bv.x; acc[2][1] += a2 * bv.y; acc[2][2] += a2 * bv.z; acc[2][3] += a2 * bv.w;
            acc[3][0] += a3 * bv.x; acc[3][1] += a3 * bv.y; acc[3][2] += a3 * bv.z; acc[3][3] += a3 * bv.w;
        }
#pragma unroll
        for (int a = 0; a < 4; a++) {
            int row = ty * 4 + a;
#pragma unroll
            for (int b = 0; b < 4; b++)
                st1[row * 68 + tx * 4 + b] = sigmoidf_(acc[a][b] + i_b1[tx * 4 + b]);
        }
    }
    __syncthreads();

    // ===== pass B: t2 = sigmoid(h @ j_w1 + j_b1), K=64 =====
    {
#pragma unroll
        for (int r = 0; r < 4; r++) {
            int i = tid + 256 * r;
            int m = i / 16, kq = i % 16;
            int gm = m0 + m;
            float4 v = make_float4(0.f, 0.f, 0.f, 0.f);
            if (gm < NN) v = *(const float4*)(hmat + (size_t)gm * 64 + kq * 4);
            int k = kq * 4;
            sA[(k + 0) * 65 + m] = v.x; sA[(k + 1) * 65 + m] = v.y;
            sA[(k + 2) * 65 + m] = v.z; sA[(k + 3) * 65 + m] = v.w;
        }
#pragma unroll
        for (int r = 0; r < 4; r++) {
            int i = tid + 256 * r;
            int k = i / 16, n4 = i % 16;
            *(float4*)(sB + k * 64 + n4 * 4) = *(const float4*)(j_w1 + (size_t)k * 64 + n4 * 4);
        }
        __syncthreads();
        float acc[4][4];
#pragma unroll
        for (int a = 0; a < 4; a++)
#pragma unroll
            for (int b = 0; b < 4; b++) acc[a][b] = 0.0f;
#pragma unroll 8
        for (int k = 0; k < 64; k++) {
            float a0 = sA[k * 65 + ty * 4 + 0];
            float a1 = sA[k * 65 + ty * 4 + 1];
            float a2 = sA[k * 65 + ty * 4 + 2];
            float a3 = sA[k * 65 + ty * 4 + 3];
            float4 bv = *(const float4*)(sB + k * 64 + tx * 4);
            acc[0][0] += a0 * bv.x; acc[0][1] += a0 * bv.y; acc[0][2] += a0 * bv.z; acc[0][3] += a0 * bv.w;
            acc[1][0] += a1 * bv.x; acc[1][1] += a1 * bv.y; acc[1][2] += a1 * bv.z; acc[1][3] += a1 * bv.w;
            acc[2][0] += a2 * bv.x; acc[2][1] += a2 * bv.y; acc[2][2] += a2 * bv.z; acc[2][3] += a2 * bv.w;
            acc[3][0] += a3 * bv.x; acc[3][1] += a3 * bv.y; acc[3][2] += a3 * bv.z; acc[3][3] += a3 * bv.w;
        }
#pragma unroll
        for (int a = 0; a < 4; a++) {
            int row = ty * 4 + a;
#pragma unroll
            for (int b = 0; b < 4; b++)
                st2[row * 68 + tx * 4 + b] = sigmoidf_(acc[a][b] + j_b1[tx * 4 + b]);
        }
    }
    __syncthreads();

    // ===== pass C: per-node DOUT projection + atomic segment-sum =====
    float* wA = sA;
    float* wB = sA + 768;
    float* bA = sA + 1536;
    float* bB = sA + 1552;
    for (int i = tid; i < 768; i += 256) { wA[i] = i_w2[i]; wB[i] = j_w2[i]; }
    if (tid < DOUT) { bA[tid] = i_b2[tid]; bB[tid] = j_b2[tid]; }
    __syncthreads();

    int ln = tid >> 2, q = tid & 3;
    int n = m0 + ln;
    if (n < NN) {
        int c0 = q * 3;
        float ai[3], aj[3];
#pragma unroll
        for (int c = 0; c < 3; c++) { ai[c] = bA[c0 + c]; aj[c] = bB[c0 + c]; }
        const float* r1 = st1 + ln * 68;
        const float* r2 = st2 + ln * 68;
#pragma unroll 4
        for (int k = 0; k < 64; k++) {
            float a = r1[k], b = r2[k];
#pragma unroll
            for (int c = 0; c < 3; c++) {
                ai[c] += a * wA[k * DOUT + c0 + c];
                aj[c] += b * wB[k * DOUT + c0 + c];
            }
        }
        float* ob = out + (size_t)batch[n] * DOUT + c0;
#pragma unroll
        for (int c = 0; c < 3; c++)
            atomicAdd(&ob[c], sigmoidf_(ai[c]) * aj[c]);
    }
}

// ---------------- launch ----------------
extern "C" void kernel_launch(void* const* d_in, const int* in_sizes, int n_in,
                              void* d_out, int out_size) {
    const float* x      = (const float*)d_in[0];
    const int*   ei     = (const int*)d_in[1];
    const int*   ea     = (const int*)d_in[2];
    const int*   batch  = (const int*)d_in[3];
    const float* lin0_w = (const float*)d_in[4];
    const float* lin0_b = (const float*)d_in[5];
    const float* eemb   = (const float*)d_in[6];
    const float* cbias  = (const float*)d_in[7];
    const float* w_ih   = (const float*)d_in[8];
    const float* w_hh   = (const float*)d_in[9];
    const float* b_ih   = (const float*)d_in[10];
    const float* b_hh   = (const float*)d_in[11];
    const float* i_w1   = (const float*)d_in[12];
    const float* i_b1   = (const float*)d_in[13];
    const float* i_w2   = (const float*)d_in[14];
    const float* i_b2   = (const float*)d_in[15];
    const float* j_w1   = (const float*)d_in[16];
    const float* j_b1   = (const float*)d_in[17];
    const float* j_w2   = (const float*)d_in[18];
    const float* j_b2   = (const float*)d_in[19];
    const int* src = ei;
    const int* dst = ei + EE;
    float* out = (float*)d_out;

    float *ph, *ph2, *pout0;
    __half *pBh, *peembh;
    int *pcnt5, *poff5, *pcur5, *ppk, *ppsum1, *ppref1, *ppsum2, *ppref2;
    cudaGetSymbolAddress((void**)&ph,     g_h);
    cudaGetSymbolAddress((void**)&ph2,    g_h2);
    cudaGetSymbolAddress((void**)&pout0,  g_out0);
    cudaGetSymbolAddress((void**)&pBh,    g_Bh);
    cudaGetSymbolAddress((void**)&peembh, g_eembh);
    cudaGetSymbolAddress((void**)&pcnt5,  g_cnt5);
    cudaGetSymbolAddress((void**)&poff5,  g_off5);
    cudaGetSymbolAddress((void**)&pcur5,  g_cur5);
    cudaGetSymbolAddress((void**)&ppk,    g_packed);
    cudaGetSymbolAddress((void**)&ppsum1, g_psum1);
    cudaGetSymbolAddress((void**)&ppref1, g_pref1);
    cudaGetSymbolAddress((void**)&ppsum2, g_psum2);
    cudaGetSymbolAddress((void**)&ppref2, g_pref2);

    cudaFuncSetAttribute(step_kernel,
                         cudaFuncAttributeMaxDynamicSharedMemorySize, GSMEM);
    cudaFuncSetAttribute(fused_readout_kernel,
                         cudaFuncAttributeMaxDynamicSharedMemorySize, RSMEM);

    // ---- once-per-call preprocessing ----
    bprep_kernel<<<7, 256>>>(eemb, w_ih, w_hh, b_ih, b_hh, pBh, peembh);
    zeroi_kernel<<<(KEYPAD + 255) / 256, 256>>>(pcnt5, KEYPAD);
    zerof_kernel<<<(GG * DOUT + 255) / 256, 256>>>(out, GG * DOUT);
    lin0_kernel<<<NN / 16, 256>>>(x, lin0_w, lin0_b, pout0, ph);
    hist5_kernel<<<(EE + 255) / 256, 256>>>(dst, ea, pcnt5);
    cs1_kernel<<<NB1, 256>>>(pcnt5, ppsum1);
    cs2_kernel<<<NB2, 256>>>(ppsum1, ppsum2);
    scan2_kernel<<<1, 32>>>(ppsum2, ppref2);
    scanB_kernel<<<NB2, 256>>>(ppsum1, ppref2, ppref1);
    offs5_kernel<<<NB1, 256>>>(pcnt5, ppref1, poff5, pcur5);
    place5_kernel<<<(EE + 255) / 256, 256>>>(src, dst, ea, pcur5, ppk);

    // ---- propagation steps (double-buffered h; 6 steps end back in g_h) ----
    float* cur = ph;
    float* nxt = ph2;
    for (int s = 0; s < STEPS; s++) {
        step_kernel<<<NCTA, 256, GSMEM>>>(cur, nxt, ppk, poff5, cbias, peembh, pBh);
        float* tmp = cur; cur = nxt; nxt = tmp;
    }

    // ---- fused readout ----
    const int MB = (NN + 63) / 64;
    fused_readout_kernel<<<MB, 256, RSMEM>>>(
        cur, pout0, batch, i_w1, i_b1, i_w2, i_b2, j_w1, j_b1, j_w2, j_b2, out);
}